// round 7
// baseline (speedup 1.0000x reference)
#include <cuda_runtime.h>
#include <cstdint>

// SinusoidPositionEncoding: out[b,s,:] = sum_m x[b,s,m] * pe[m,:]
// x one-hot over m (4096). Early-exit chunked scan (R4: 56% traffic confirmed),
// 2-row interleave per warp (R6: 8 LDG.128 in flight), and NEW in R7:
// dynamic work-stealing over row-pairs via a global atomic counter to kill
// the wave-quantization + duration-variance tail (R6: 1.73 uneven waves).
// x (8,2048,4096) f32, pe (4096,128) f32, out (8,2048,128) f32.

#define N_ROWS (8 * 2048)   // 16384
#define N_PAIRS (N_ROWS / 2)
#define M_VEC  1024         // 4096/4 float4 per row
#define D_VEC  32           // 128/4
#define CHUNK_LOADS 4       // 4 x LDG.128 per lane per chunk = 512 floats
#define N_CHUNKS 8

__device__ unsigned g_pair_ctr;

__global__ void pe_reset_ctr() { g_pair_ctr = 0u; }

__device__ __forceinline__ void gather_pe(const float4* __restrict__ pe,
                                          unsigned mask, int hitpos, uint4 hitv,
                                          int lane, float4& acc) {
    while (mask) {
        const int src = __ffs(mask) - 1;
        mask &= mask - 1;
        const int   p  = __shfl_sync(0xffffffffu, hitpos, src);
        const float vx = __uint_as_float(__shfl_sync(0xffffffffu, hitv.x, src));
        const float vy = __uint_as_float(__shfl_sync(0xffffffffu, hitv.y, src));
        const float vz = __uint_as_float(__shfl_sync(0xffffffffu, hitv.z, src));
        const float vw = __uint_as_float(__shfl_sync(0xffffffffu, hitv.w, src));
        const int e = p * 4;
        if (__float_as_uint(vx) != 0u) {
            const float4 pr = __ldg(&pe[(size_t)(e + 0) * D_VEC + lane]);
            acc.x += vx * pr.x; acc.y += vx * pr.y; acc.z += vx * pr.z; acc.w += vx * pr.w;
        }
        if (__float_as_uint(vy) != 0u) {
            const float4 pr = __ldg(&pe[(size_t)(e + 1) * D_VEC + lane]);
            acc.x += vy * pr.x; acc.y += vy * pr.y; acc.z += vy * pr.z; acc.w += vy * pr.w;
        }
        if (__float_as_uint(vz) != 0u) {
            const float4 pr = __ldg(&pe[(size_t)(e + 2) * D_VEC + lane]);
            acc.x += vz * pr.x; acc.y += vz * pr.y; acc.z += vz * pr.z; acc.w += vz * pr.w;
        }
        if (__float_as_uint(vw) != 0u) {
            const float4 pr = __ldg(&pe[(size_t)(e + 3) * D_VEC + lane]);
            acc.x += vw * pr.x; acc.y += vw * pr.y; acc.z += vw * pr.z; acc.w += vw * pr.w;
        }
    }
}

__global__ __launch_bounds__(256, 4)
void pe_onehot_ws_kernel(const uint4* __restrict__ x,
                         const float4* __restrict__ pe,
                         float4* __restrict__ out) {
    const int lane = threadIdx.x & 31;

    for (;;) {
        // ---- steal a pair of adjacent rows ----
        unsigned pair;
        if (lane == 0) pair = atomicAdd(&g_pair_ctr, 1u);
        pair = __shfl_sync(0xffffffffu, pair, 0);
        if (pair >= N_PAIRS) return;

        const int rowA = (int)pair * 2;
        const int rowB = rowA + 1;
        const uint4* xA = x + (size_t)rowA * M_VEC;
        const uint4* xB = x + (size_t)rowB * M_VEC;

        uint4 hvA = make_uint4(0u,0u,0u,0u), hvB = make_uint4(0u,0u,0u,0u);
        int hpA = -1, hpB = -1;
        unsigned ballA = 0u, ballB = 0u;

        for (int c = 0; c < N_CHUNKS; c++) {
            const int base = c * (CHUNK_LOADS * 32);
            const bool actA = (ballA == 0u);   // warp-uniform
            const bool actB = (ballB == 0u);   // warp-uniform
            uint4 vA[CHUNK_LOADS], vB[CHUNK_LOADS];

            if (actA) {
                #pragma unroll
                for (int j = 0; j < CHUNK_LOADS; j++)
                    vA[j] = __ldcs(&xA[base + j * 32 + lane]);
            }
            if (actB) {
                #pragma unroll
                for (int j = 0; j < CHUNK_LOADS; j++)
                    vB[j] = __ldcs(&xB[base + j * 32 + lane]);
            }
            if (actA) {
                #pragma unroll
                for (int j = 0; j < CHUNK_LOADS; j++)
                    if ((vA[j].x | vA[j].y | vA[j].z | vA[j].w) != 0u) {
                        hvA = vA[j]; hpA = base + j * 32 + lane;
                    }
                ballA = __ballot_sync(0xffffffffu, hpA >= 0);
            }
            if (actB) {
                #pragma unroll
                for (int j = 0; j < CHUNK_LOADS; j++)
                    if ((vB[j].x | vB[j].y | vB[j].z | vB[j].w) != 0u) {
                        hvB = vB[j]; hpB = base + j * 32 + lane;
                    }
                ballB = __ballot_sync(0xffffffffu, hpB >= 0);
            }
            if (ballA && ballB) break;
        }

        float4 accA = make_float4(0.f,0.f,0.f,0.f);
        float4 accB = make_float4(0.f,0.f,0.f,0.f);
        gather_pe(pe, ballA, hpA, hvA, lane, accA);
        gather_pe(pe, ballB, hpB, hvB, lane, accB);

        __stcs(&out[(size_t)rowA * D_VEC + lane], accA);
        __stcs(&out[(size_t)rowB * D_VEC + lane], accB);
    }
}

extern "C" void kernel_launch(void* const* d_in, const int* in_sizes, int n_in,
                              void* d_out, int out_size) {
    const uint4*  x  = (const uint4*)d_in[0];    // (8,2048,4096) f32
    const float4* pe = (const float4*)d_in[1];   // (4096,128)    f32
    float4* out = (float4*)d_out;                // (8,2048,128)  f32

    pe_reset_ctr<<<1, 1>>>();
    // 148 SMs x 4 blocks/SM = 592 blocks: exactly one resident wave;
    // work distribution handled by the atomic counter.
    pe_onehot_ws_kernel<<<592, 256>>>(x, pe, out);
}

// round 8
// speedup vs baseline: 1.0593x; 1.0593x over previous
#include <cuda_runtime.h>
#include <cstdint>

// SinusoidPositionEncoding: out[b,s,:] = sum_m x[b,s,m] * pe[m,:]
// x one-hot over m (4096). Early-exit chunked scan (R4: 56% x-traffic confirmed),
// 2-row interleave (R6: 8 LDG.128 in flight). R8:
//  - __launch_bounds__(256,5): regs<=51 -> 5 blocks/SM -> ~240 in-flight loads/SM
//  - grid 740 = 148*5: exactly one wave, statically balanced per-warp pairs
//    {w, w+5920}, rows (2p,2p+1) keep block-contiguous DRAM streaming.
// No atomics (R7 stealing regressed). x (8,2048,4096) f32, pe (4096,128) f32,
// out (8,2048,128) f32.

#define N_ROWS (8 * 2048)    // 16384
#define N_PAIRS (N_ROWS / 2) // 8192
#define M_VEC  1024          // 4096/4 float4 per row
#define D_VEC  32            // 128/4
#define CHUNK_LOADS 4        // 4 x LDG.128 per lane per chunk = 512 floats
#define N_CHUNKS 8
#define GRID_BLOCKS 740      // 148 SMs * 5 blocks
#define TOTAL_WARPS (GRID_BLOCKS * 8)   // 5920

__device__ __forceinline__ void gather_pe(const float4* __restrict__ pe,
                                          unsigned mask, int hitpos, uint4 hitv,
                                          int lane, float4& acc) {
    while (mask) {
        const int src = __ffs(mask) - 1;
        mask &= mask - 1;
        const int   p  = __shfl_sync(0xffffffffu, hitpos, src);
        const float vx = __uint_as_float(__shfl_sync(0xffffffffu, hitv.x, src));
        const float vy = __uint_as_float(__shfl_sync(0xffffffffu, hitv.y, src));
        const float vz = __uint_as_float(__shfl_sync(0xffffffffu, hitv.z, src));
        const float vw = __uint_as_float(__shfl_sync(0xffffffffu, hitv.w, src));
        const int e = p * 4;
        if (__float_as_uint(vx) != 0u) {
            const float4 pr = __ldg(&pe[(size_t)(e + 0) * D_VEC + lane]);
            acc.x += vx * pr.x; acc.y += vx * pr.y; acc.z += vx * pr.z; acc.w += vx * pr.w;
        }
        if (__float_as_uint(vy) != 0u) {
            const float4 pr = __ldg(&pe[(size_t)(e + 1) * D_VEC + lane]);
            acc.x += vy * pr.x; acc.y += vy * pr.y; acc.z += vy * pr.z; acc.w += vy * pr.w;
        }
        if (__float_as_uint(vz) != 0u) {
            const float4 pr = __ldg(&pe[(size_t)(e + 2) * D_VEC + lane]);
            acc.x += vz * pr.x; acc.y += vz * pr.y; acc.z += vz * pr.z; acc.w += vz * pr.w;
        }
        if (__float_as_uint(vw) != 0u) {
            const float4 pr = __ldg(&pe[(size_t)(e + 3) * D_VEC + lane]);
            acc.x += vw * pr.x; acc.y += vw * pr.y; acc.z += vw * pr.z; acc.w += vw * pr.w;
        }
    }
}

__device__ __forceinline__ void process_pair(const uint4* __restrict__ x,
                                             const float4* __restrict__ pe,
                                             float4* __restrict__ out,
                                             int pair, int lane) {
    const int rowA = pair * 2;
    const int rowB = rowA + 1;
    const uint4* xA = x + (size_t)rowA * M_VEC;
    const uint4* xB = x + (size_t)rowB * M_VEC;

    uint4 hvA = make_uint4(0u,0u,0u,0u), hvB = make_uint4(0u,0u,0u,0u);
    int hpA = -1, hpB = -1;
    unsigned ballA = 0u, ballB = 0u;

    for (int c = 0; c < N_CHUNKS; c++) {
        const int base = c * (CHUNK_LOADS * 32);
        const bool actA = (ballA == 0u);   // warp-uniform
        const bool actB = (ballB == 0u);   // warp-uniform
        uint4 vA[CHUNK_LOADS], vB[CHUNK_LOADS];

        if (actA) {
            #pragma unroll
            for (int j = 0; j < CHUNK_LOADS; j++)
                vA[j] = __ldcs(&xA[base + j * 32 + lane]);
        }
        if (actB) {
            #pragma unroll
            for (int j = 0; j < CHUNK_LOADS; j++)
                vB[j] = __ldcs(&xB[base + j * 32 + lane]);
        }
        if (actA) {
            #pragma unroll
            for (int j = 0; j < CHUNK_LOADS; j++)
                if ((vA[j].x | vA[j].y | vA[j].z | vA[j].w) != 0u) {
                    hvA = vA[j]; hpA = base + j * 32 + lane;
                }
            ballA = __ballot_sync(0xffffffffu, hpA >= 0);
        }
        if (actB) {
            #pragma unroll
            for (int j = 0; j < CHUNK_LOADS; j++)
                if ((vB[j].x | vB[j].y | vB[j].z | vB[j].w) != 0u) {
                    hvB = vB[j]; hpB = base + j * 32 + lane;
                }
            ballB = __ballot_sync(0xffffffffu, hpB >= 0);
        }
        if (ballA && ballB) break;
    }

    float4 accA = make_float4(0.f,0.f,0.f,0.f);
    float4 accB = make_float4(0.f,0.f,0.f,0.f);
    gather_pe(pe, ballA, hpA, hvA, lane, accA);
    gather_pe(pe, ballB, hpB, hvB, lane, accB);

    __stcs(&out[(size_t)rowA * D_VEC + lane], accA);
    __stcs(&out[(size_t)rowB * D_VEC + lane], accB);
}

__global__ __launch_bounds__(256, 5)
void pe_onehot_1wave_kernel(const uint4* __restrict__ x,
                            const float4* __restrict__ pe,
                            float4* __restrict__ out) {
    const int lane = threadIdx.x & 31;
    const int gw   = blockIdx.x * 8 + (threadIdx.x >> 5);  // 0..5919

    // First pair: one per warp, block-contiguous rows.
    process_pair(x, pe, out, gw, lane);
    // Second pair for the first 8192-5920=2272 warps.
    const int p2 = gw + TOTAL_WARPS;
    if (p2 < N_PAIRS) process_pair(x, pe, out, p2, lane);
}

extern "C" void kernel_launch(void* const* d_in, const int* in_sizes, int n_in,
                              void* d_out, int out_size) {
    const uint4*  x  = (const uint4*)d_in[0];    // (8,2048,4096) f32
    const float4* pe = (const float4*)d_in[1];   // (4096,128)    f32
    float4* out = (float4*)d_out;                // (8,2048,128)  f32

    pe_onehot_1wave_kernel<<<GRID_BLOCKS, 256>>>(x, pe, out);
}

// round 9
// speedup vs baseline: 1.1227x; 1.0598x over previous
#include <cuda_runtime.h>
#include <cstdint>

// SinusoidPositionEncoding: out[b,s,:] = sum_m x[b,s,m] * pe[m,:]
// x one-hot over m (4096). Early-exit chunked scan (R4: ~56% x-traffic, confirmed),
// 2-row interleave per warp (R6). R9: 128-thread blocks, grid 2048 (~1.5 waves,
// ~9 blocks/SM) -> finer hardware backfill granularity to shrink the drain tail
// that capped R6 at 5.28 TB/s. No atomics (R7 regressed), no single-wave static
// schedule (R8 regressed: no backfill).
// x (8,2048,4096) f32, pe (4096,128) f32, out (8,2048,128) f32.

#define N_ROWS (8 * 2048)   // 16384
#define M_VEC  1024         // 4096/4 float4 per row
#define D_VEC  32           // 128/4
#define CHUNK_LOADS 4       // 4 x LDG.128 per lane per chunk = 512 floats
#define N_CHUNKS 8
#define WARPS_PER_BLOCK 4   // 128 threads
#define ROWS_PER_BLOCK (WARPS_PER_BLOCK * 2)   // 8

__device__ __forceinline__ void gather_pe(const float4* __restrict__ pe,
                                          unsigned mask, int hitpos, uint4 hitv,
                                          int lane, float4& acc) {
    while (mask) {
        const int src = __ffs(mask) - 1;
        mask &= mask - 1;
        const int   p  = __shfl_sync(0xffffffffu, hitpos, src);
        const float vx = __uint_as_float(__shfl_sync(0xffffffffu, hitv.x, src));
        const float vy = __uint_as_float(__shfl_sync(0xffffffffu, hitv.y, src));
        const float vz = __uint_as_float(__shfl_sync(0xffffffffu, hitv.z, src));
        const float vw = __uint_as_float(__shfl_sync(0xffffffffu, hitv.w, src));
        const int e = p * 4;
        if (__float_as_uint(vx) != 0u) {
            const float4 pr = __ldg(&pe[(size_t)(e + 0) * D_VEC + lane]);
            acc.x += vx * pr.x; acc.y += vx * pr.y; acc.z += vx * pr.z; acc.w += vx * pr.w;
        }
        if (__float_as_uint(vy) != 0u) {
            const float4 pr = __ldg(&pe[(size_t)(e + 1) * D_VEC + lane]);
            acc.x += vy * pr.x; acc.y += vy * pr.y; acc.z += vy * pr.z; acc.w += vy * pr.w;
        }
        if (__float_as_uint(vz) != 0u) {
            const float4 pr = __ldg(&pe[(size_t)(e + 2) * D_VEC + lane]);
            acc.x += vz * pr.x; acc.y += vz * pr.y; acc.z += vz * pr.z; acc.w += vz * pr.w;
        }
        if (__float_as_uint(vw) != 0u) {
            const float4 pr = __ldg(&pe[(size_t)(e + 3) * D_VEC + lane]);
            acc.x += vw * pr.x; acc.y += vw * pr.y; acc.z += vw * pr.z; acc.w += vw * pr.w;
        }
    }
}

__global__ __launch_bounds__(128)
void pe_onehot_gather2_kernel(const uint4* __restrict__ x,
                              const float4* __restrict__ pe,
                              float4* __restrict__ out) {
    const int warp = threadIdx.x >> 5;
    const int lane = threadIdx.x & 31;
    // Block owns 8 contiguous rows; warp w owns rows base+w and base+w+4.
    const int rowA = blockIdx.x * ROWS_PER_BLOCK + warp;
    const int rowB = rowA + WARPS_PER_BLOCK;

    const uint4* xA = x + (size_t)rowA * M_VEC;
    const uint4* xB = x + (size_t)rowB * M_VEC;

    uint4 hvA = make_uint4(0u,0u,0u,0u), hvB = make_uint4(0u,0u,0u,0u);
    int hpA = -1, hpB = -1;
    unsigned ballA = 0u, ballB = 0u;

    for (int c = 0; c < N_CHUNKS; c++) {
        const int base = c * (CHUNK_LOADS * 32);
        const bool actA = (ballA == 0u);   // warp-uniform
        const bool actB = (ballB == 0u);   // warp-uniform
        uint4 vA[CHUNK_LOADS], vB[CHUNK_LOADS];

        if (actA) {
            #pragma unroll
            for (int j = 0; j < CHUNK_LOADS; j++)
                vA[j] = __ldcs(&xA[base + j * 32 + lane]);
        }
        if (actB) {
            #pragma unroll
            for (int j = 0; j < CHUNK_LOADS; j++)
                vB[j] = __ldcs(&xB[base + j * 32 + lane]);
        }
        if (actA) {
            #pragma unroll
            for (int j = 0; j < CHUNK_LOADS; j++)
                if ((vA[j].x | vA[j].y | vA[j].z | vA[j].w) != 0u) {
                    hvA = vA[j]; hpA = base + j * 32 + lane;
                }
            ballA = __ballot_sync(0xffffffffu, hpA >= 0);
        }
        if (actB) {
            #pragma unroll
            for (int j = 0; j < CHUNK_LOADS; j++)
                if ((vB[j].x | vB[j].y | vB[j].z | vB[j].w) != 0u) {
                    hvB = vB[j]; hpB = base + j * 32 + lane;
                }
            ballB = __ballot_sync(0xffffffffu, hpB >= 0);
        }
        if (ballA && ballB) break;
    }

    float4 accA = make_float4(0.f,0.f,0.f,0.f);
    float4 accB = make_float4(0.f,0.f,0.f,0.f);
    gather_pe(pe, ballA, hpA, hvA, lane, accA);
    gather_pe(pe, ballB, hpB, hvB, lane, accB);

    __stcs(&out[(size_t)rowA * D_VEC + lane], accA);
    __stcs(&out[(size_t)rowB * D_VEC + lane], accB);
}

extern "C" void kernel_launch(void* const* d_in, const int* in_sizes, int n_in,
                              void* d_out, int out_size) {
    const uint4*  x  = (const uint4*)d_in[0];    // (8,2048,4096) f32
    const float4* pe = (const float4*)d_in[1];   // (4096,128)    f32
    float4* out = (float4*)d_out;                // (8,2048,128)  f32

    const int grid = N_ROWS / ROWS_PER_BLOCK;    // 2048 blocks of 128 threads
    pe_onehot_gather2_kernel<<<grid, 128>>>(x, pe, out);
}